// round 3
// baseline (speedup 1.0000x reference)
#include <cuda_runtime.h>
#include <math.h>

#define VOCAB 50257
#define DIM   128
#define HID   128
#define GATES 512
#define BATCH 64
#define SEQ   2048

typedef unsigned long long ull;

// Permuted projected table: P2[v][256*r + 4*u + g] = emb[v]@W_ih[row] + b,
// where row = g*128 + 64*r + u.  (lstm thread j of rank r reads col 256r+j.)
__device__ float g_P[(size_t)VOCAB * GATES];

#define FMA2(acc, a, b) \
    asm("fma.rn.f32x2 %0, %1, %2, %0;" : "+l"(acc) : "l"(a), "l"(b))

// ---------------------------------------------------------------------------
// Kernel 1: P2 = permute(emb @ W_ih^T + b), f32x2 inner loop
// ---------------------------------------------------------------------------
__global__ __launch_bounds__(256) void proj_kernel(
    const float* __restrict__ emb,
    const float* __restrict__ W_ih,
    const float* __restrict__ b_ih,
    const float* __restrict__ b_hh)
{
    extern __shared__ float sm1[];
    float* As = sm1;               // [64][130]  (130 -> 8B-aligned rows)
    float* Bs = sm1 + 64 * 130;    // [64][130]

    const int tid  = threadIdx.x;
    const int tx   = tid & 15;
    const int ty   = tid >> 4;
    const int row0 = blockIdx.y << 6;
    const int n0   = blockIdx.x << 6;

    #pragma unroll
    for (int i = 0; i < 8; ++i) {
        int idx = tid + (i << 8);
        int m   = idx >> 5;
        int k4  = (idx & 31) << 2;
        int gm  = row0 + m;
        float4 a = make_float4(0.f, 0.f, 0.f, 0.f);
        if (gm < VOCAB)
            a = *reinterpret_cast<const float4*>(emb + (size_t)gm * DIM + k4);
        As[m * 130 + k4 + 0] = a.x;
        As[m * 130 + k4 + 1] = a.y;
        As[m * 130 + k4 + 2] = a.z;
        As[m * 130 + k4 + 3] = a.w;
        float4 w = *reinterpret_cast<const float4*>(W_ih + (size_t)(n0 + m) * DIM + k4);
        Bs[m * 130 + k4 + 0] = w.x;
        Bs[m * 130 + k4 + 1] = w.y;
        Bs[m * 130 + k4 + 2] = w.z;
        Bs[m * 130 + k4 + 3] = w.w;
    }
    __syncthreads();

    ull acc2[4][4];
    #pragma unroll
    for (int i = 0; i < 4; ++i)
        #pragma unroll
        for (int jj = 0; jj < 4; ++jj) acc2[i][jj] = 0ull;

    const ull* ap = (const ull*)As + (ty << 2) * 65;   // row stride 65 ull
    const ull* bp = (const ull*)Bs + (tx << 2) * 65;

    #pragma unroll 4
    for (int k2 = 0; k2 < 64; ++k2) {
        ull a0 = ap[k2], a1 = ap[k2 + 65], a2 = ap[k2 + 130], a3 = ap[k2 + 195];
        ull b0 = bp[k2], b1 = bp[k2 + 65], b2 = bp[k2 + 130], b3 = bp[k2 + 195];
        FMA2(acc2[0][0], a0, b0); FMA2(acc2[0][1], a0, b1);
        FMA2(acc2[0][2], a0, b2); FMA2(acc2[0][3], a0, b3);
        FMA2(acc2[1][0], a1, b0); FMA2(acc2[1][1], a1, b1);
        FMA2(acc2[1][2], a1, b2); FMA2(acc2[1][3], a1, b3);
        FMA2(acc2[2][0], a2, b0); FMA2(acc2[2][1], a2, b1);
        FMA2(acc2[2][2], a2, b2); FMA2(acc2[2][3], a2, b3);
        FMA2(acc2[3][0], a3, b0); FMA2(acc2[3][1], a3, b1);
        FMA2(acc2[3][2], a3, b2); FMA2(acc2[3][3], a3, b3);
    }

    const int gn = n0 + (tx << 2);
    float bb[4];
    #pragma unroll
    for (int m = 0; m < 4; ++m) bb[m] = b_ih[gn + m] + b_hh[gn + m];

    // permuted destination: col -> (r<<8) + (u<<2) + g
    const int gg  = gn >> 7;
    const int rr  = (gn >> 6) & 1;
    const int uu  = gn & 63;
    const int nc0 = (rr << 8) + (uu << 2) + gg;

    #pragma unroll
    for (int i = 0; i < 4; ++i) {
        int gm = row0 + (ty << 2) + i;
        if (gm < VOCAB) {
            #pragma unroll
            for (int m = 0; m < 4; ++m) {
                float lo, hi;
                asm("mov.b64 {%0,%1}, %2;" : "=f"(lo), "=f"(hi) : "l"(acc2[i][m]));
                g_P[(size_t)gm * GATES + nc0 + (m << 2)] = lo + hi + bb[m];
            }
        }
    }
}

// ---------------------------------------------------------------------------
// Kernel 2: recurrent LSTM, cluster-of-2 UNIT-split.
//   Rank r owns h/c units [64r,64r+64). 256 threads; thread j: gate g=j&3,
//   unit u=j>>2, full 128-k weight row in registers. Local-half matvec runs
//   while peer's 64 h (256 B, st.async b64) are in flight; shuffle-based tail.
// ---------------------------------------------------------------------------
__device__ __forceinline__ float sig_f(float x) {
    return __fdividef(1.f, 1.f + __expf(-x));
}
__device__ __forceinline__ float tanh_f(float x) {
    float e = __expf(fminf(-2.f * x, 30.f));
    return __fdividef(1.f - e, 1.f + e);
}
__device__ __forceinline__ unsigned cvta_smem(const void* p) {
    unsigned r;
    asm("{ .reg .u64 t; cvta.to.shared.u64 t, %1; cvt.u32.u64 %0, t; }"
        : "=r"(r) : "l"(p));
    return r;
}

#define MBWAIT(addr, par) do {                                                 \
    unsigned _done;                                                            \
    asm volatile(                                                              \
        "{\n\t.reg .pred p;\n\t"                                               \
        "mbarrier.try_wait.parity.acquire.cta.shared::cta.b64 p, [%1], %2;\n\t" \
        "selp.b32 %0, 1, 0, p;\n\t}"                                           \
        : "=r"(_done) : "r"(addr), "r"(par) : "memory");                       \
    if (!_done) {                                                              \
        asm volatile(                                                          \
            "{\n\t.reg .pred P1;\n\t"                                          \
            "WL_%=:\n\t"                                                       \
            "mbarrier.try_wait.parity.acquire.cta.shared::cta.b64 P1, [%0], %1, 0x989680;\n\t" \
            "@P1 bra.uni WD_%=;\n\t"                                           \
            "bra.uni WL_%=;\n\t"                                               \
            "WD_%=:\n\t}"                                                      \
            :: "r"(addr), "r"(par) : "memory");                                \
    }                                                                          \
} while (0)

// half-K matvec with literal weight offset (keeps wreg in registers)
#define MV_HALF(OFF, HP) do {                                                  \
    const ulonglong2* _hp = (HP);                                              \
    _Pragma("unroll")                                                          \
    for (int q = 0; q < 8; ++q) {                                              \
        ulonglong2 A = _hp[2 * q];                                             \
        ulonglong2 B = _hp[2 * q + 1];                                         \
        FMA2(a0, wreg[(OFF) + 4 * q + 0], A.x);                                \
        FMA2(a1, wreg[(OFF) + 4 * q + 1], A.y);                                \
        FMA2(a2, wreg[(OFF) + 4 * q + 2], B.x);                                \
        FMA2(a3, wreg[(OFF) + 4 * q + 3], B.y);                                \
    }                                                                          \
} while (0)

__global__ __launch_bounds__(256, 1) __cluster_dims__(2, 1, 1)
void lstm_kernel(
    const int*   __restrict__ tokens,
    const float* __restrict__ W_hh,
    float*       __restrict__ out)
{
    __shared__ __align__(16) float h_s[2][128];
    __shared__ __align__(16) ull   mb_peer[2];
    __shared__ int tok_s[SEQ];

    const int j    = threadIdx.x;          // 0..255
    const int b    = blockIdx.x >> 1;
    const int rank = blockIdx.x & 1;
    const int peer = rank ^ 1;
    const int g    = j & 3;
    const int u    = j >> 2;               // local unit 0..63
    const int row  = g * 128 + rank * 64 + u;

    const ull* W64 = (const ull*)W_hh;
    ull wreg[64];
    #pragma unroll
    for (int kk = 0; kk < 64; ++kk)
        wreg[kk] = W64[(size_t)row * 64 + kk];

    for (int idx = j; idx < SEQ; idx += 256)
        tok_s[idx] = tokens[(size_t)b * SEQ + idx];

    const unsigned mb_a = cvta_smem(mb_peer);
    if (j == 0) {
        asm volatile("mbarrier.init.shared.b64 [%0], %1;" :: "r"(mb_a), "r"(1u) : "memory");
        asm volatile("mbarrier.init.shared.b64 [%0], %1;" :: "r"(mb_a + 8), "r"(1u) : "memory");
        asm volatile("mbarrier.arrive.expect_tx.shared.b64 _, [%0], %1;" :: "r"(mb_a), "r"(256u) : "memory");
        asm volatile("mbarrier.arrive.expect_tx.shared.b64 _, [%0], %1;" :: "r"(mb_a + 8), "r"(256u) : "memory");
    }
    __syncthreads();
    asm volatile("barrier.cluster.arrive.aligned;" ::: "memory");
    asm volatile("barrier.cluster.wait.aligned;"   ::: "memory");

    unsigned rm_h, rm_mb;
    {
        unsigned h_a = cvta_smem(h_s);
        asm("mapa.shared::cluster.u32 %0, %1, %2;" : "=r"(rm_h)  : "r"(h_a),  "r"(peer));
        asm("mapa.shared::cluster.u32 %0, %1, %2;" : "=r"(rm_mb) : "r"(mb_a), "r"(peer));
    }

    const float* Pp = (const float*)g_P;
    float x_cur = __ldg(Pp + (size_t)tok_s[0] * GATES + rank * 256 + j);
    float c = 0.f;
    unsigned ph0 = 0, ph1 = 0;

    for (int t = 0; t < SEQ; ++t) {
        const int buf = t & 1;
        float xg = x_cur;
        if (t + 1 < SEQ)
            x_cur = __ldg(Pp + (size_t)tok_s[t + 1] * GATES + rank * 256 + j);

        float gsum = xg;
        if (t > 0) {
            ull a0 = 0ull, a1 = 0ull, a2 = 0ull, a3 = 0ull;
            const ulonglong2* h_loc = (const ulonglong2*)&h_s[buf][rank * 64];
            const ulonglong2* h_rem = (const ulonglong2*)&h_s[buf][peer * 64];

            if (rank == 0) {
                MV_HALF(0, h_loc);                       // own k first (no wait)
                unsigned par = buf ? ph1 : ph0;
                MBWAIT(mb_a + (unsigned)(buf << 3), par);
                if (buf) ph1 ^= 1; else ph0 ^= 1;
                if (j == 0)
                    asm volatile("mbarrier.arrive.expect_tx.shared.b64 _, [%0], %1;"
                                 :: "r"(mb_a + (unsigned)(buf << 3)), "r"(256u) : "memory");
                MV_HALF(32, h_rem);
            } else {
                MV_HALF(32, h_loc);
                unsigned par = buf ? ph1 : ph0;
                MBWAIT(mb_a + (unsigned)(buf << 3), par);
                if (buf) ph1 ^= 1; else ph0 ^= 1;
                if (j == 0)
                    asm volatile("mbarrier.arrive.expect_tx.shared.b64 _, [%0], %1;"
                                 :: "r"(mb_a + (unsigned)(buf << 3)), "r"(256u) : "memory");
                MV_HALF(0, h_rem);
            }

            float s0, s1, s2, s3, s4, s5, s6, s7;
            asm("mov.b64 {%0,%1}, %2;" : "=f"(s0), "=f"(s1) : "l"(a0));
            asm("mov.b64 {%0,%1}, %2;" : "=f"(s2), "=f"(s3) : "l"(a1));
            asm("mov.b64 {%0,%1}, %2;" : "=f"(s4), "=f"(s5) : "l"(a2));
            asm("mov.b64 {%0,%1}, %2;" : "=f"(s6), "=f"(s7) : "l"(a3));
            gsum += ((s0 + s1) + (s2 + s3)) + ((s4 + s5) + (s6 + s7));
        }

        float act = (g == 2) ? tanh_f(gsum) : sig_f(gsum);
        // share the 4 gate activations within the lane group of 4
        float x1 = __shfl_xor_sync(0xFFFFFFFFu, act, 1);
        float x2 = __shfl_xor_sync(0xFFFFFFFFu, act, 2);
        float x3 = __shfl_xor_sync(0xFFFFFFFFu, x1, 2);
        float ai  = (g == 0) ? act : (g == 1) ? x1 : (g == 2) ? x2 : x3;
        float af  = (g == 1) ? act : (g == 0) ? x1 : (g == 3) ? x2 : x3;
        float agv = (g == 2) ? act : (g == 3) ? x1 : (g == 0) ? x2 : x3;
        float ao  = (g == 3) ? act : (g == 2) ? x1 : (g == 1) ? x2 : x3;

        c = fmaf(af, c, ai * agv);           // identical in all 4 lanes of a unit
        float hn = 0.f;
        if (g == 0) hn = ao * tanh_f(c);     // only owner lanes need h
        float hn2 = __shfl_down_sync(0xFFFFFFFFu, hn, 4);   // h of unit u+1

        if (t + 1 < SEQ) {
            const int buf2 = buf ^ 1;
            if ((j & 7) == 0) {              // 32 senders: units (u, u+1)
                *(float2*)&h_s[buf2][rank * 64 + u] = make_float2(hn, hn2);
                ull pk;
                asm("mov.b64 %0, {%1,%2};" : "=l"(pk) : "f"(hn), "f"(hn2));
                unsigned dst = rm_h + (unsigned)(((buf2 << 7) + rank * 64 + u) << 2);
                asm volatile(
                    "st.async.shared::cluster.mbarrier::complete_tx::bytes.b64 [%0], %1, [%2];"
                    :: "r"(dst), "l"(pk), "r"(rm_mb + (unsigned)(buf2 << 3)) : "memory");
            }
            __syncthreads();                 // publish local STS for next step
        } else {
            if (g == 0) {
                out[(size_t)b * HID + rank * 64 + u] = hn;
                out[(size_t)BATCH * HID + (size_t)b * HID + rank * 64 + u] = c;
            }
        }
    }

    asm volatile("barrier.cluster.arrive.aligned;" ::: "memory");
    asm volatile("barrier.cluster.wait.aligned;"   ::: "memory");
}

// ---------------------------------------------------------------------------
extern "C" void kernel_launch(void* const* d_in, const int* in_sizes, int n_in,
                              void* d_out, int out_size)
{
    const int*   tokens = (const int*)  d_in[0];
    const float* emb    = (const float*)d_in[1];
    const float* W_ih   = (const float*)d_in[2];
    const float* W_hh   = (const float*)d_in[3];
    const float* b_ih   = (const float*)d_in[4];
    const float* b_hh   = (const float*)d_in[5];
    float* out = (float*)d_out;

    const int smem1 = 2 * 64 * 130 * (int)sizeof(float);   // 66560 B
    cudaFuncSetAttribute(proj_kernel, cudaFuncAttributeMaxDynamicSharedMemorySize, smem1);

    dim3 g1(GATES / 64, (VOCAB + 63) / 64);
    proj_kernel<<<g1, 256, smem1>>>(emb, W_ih, b_ih, b_hh);
    lstm_kernel<<<BATCH * 2, 256>>>(tokens, W_hh, out);
}

// round 4
// speedup vs baseline: 1.1916x; 1.1916x over previous
#include <cuda_runtime.h>
#include <math.h>

#define VOCAB 50257
#define DIM   128
#define HID   128
#define GATES 512
#define BATCH 64
#define SEQ   2048

typedef unsigned long long ull;

// Projected embedding table: P[v][g] = dot(emb[v], W_ih[g]) + b_ih[g] + b_hh[g]
__device__ float g_P[(size_t)VOCAB * GATES];

#define FMA2(acc, a, b) \
    asm("fma.rn.f32x2 %0, %1, %2, %0;" : "+l"(acc) : "l"(a), "l"(b))

// ---------------------------------------------------------------------------
// Kernel 1: P = emb @ W_ih^T + b, f32x2 inner loop, float4 stores
// ---------------------------------------------------------------------------
__global__ __launch_bounds__(256) void proj_kernel(
    const float* __restrict__ emb,
    const float* __restrict__ W_ih,
    const float* __restrict__ b_ih,
    const float* __restrict__ b_hh)
{
    extern __shared__ float sm1[];
    float* As = sm1;               // [64][130] (8B-aligned rows)
    float* Bs = sm1 + 64 * 130;    // [64][130]

    const int tid  = threadIdx.x;
    const int tx   = tid & 15;
    const int ty   = tid >> 4;
    const int row0 = blockIdx.y << 6;
    const int n0   = blockIdx.x << 6;

    #pragma unroll
    for (int i = 0; i < 8; ++i) {
        int idx = tid + (i << 8);
        int m   = idx >> 5;
        int k4  = (idx & 31) << 2;
        int gm  = row0 + m;
        float4 a = make_float4(0.f, 0.f, 0.f, 0.f);
        if (gm < VOCAB)
            a = *reinterpret_cast<const float4*>(emb + (size_t)gm * DIM + k4);
        As[m * 130 + k4 + 0] = a.x;
        As[m * 130 + k4 + 1] = a.y;
        As[m * 130 + k4 + 2] = a.z;
        As[m * 130 + k4 + 3] = a.w;
        float4 w = *reinterpret_cast<const float4*>(W_ih + (size_t)(n0 + m) * DIM + k4);
        Bs[m * 130 + k4 + 0] = w.x;
        Bs[m * 130 + k4 + 1] = w.y;
        Bs[m * 130 + k4 + 2] = w.z;
        Bs[m * 130 + k4 + 3] = w.w;
    }
    __syncthreads();

    ull acc2[4][4];
    #pragma unroll
    for (int i = 0; i < 4; ++i)
        #pragma unroll
        for (int jj = 0; jj < 4; ++jj) acc2[i][jj] = 0ull;

    const ull* ap = (const ull*)As + (ty << 2) * 65;   // row stride 65 ull
    const ull* bp = (const ull*)Bs + (tx << 2) * 65;

    #pragma unroll 4
    for (int k2 = 0; k2 < 64; ++k2) {
        ull a0 = ap[k2], a1 = ap[k2 + 65], a2 = ap[k2 + 130], a3 = ap[k2 + 195];
        ull b0 = bp[k2], b1 = bp[k2 + 65], b2 = bp[k2 + 130], b3 = bp[k2 + 195];
        FMA2(acc2[0][0], a0, b0); FMA2(acc2[0][1], a0, b1);
        FMA2(acc2[0][2], a0, b2); FMA2(acc2[0][3], a0, b3);
        FMA2(acc2[1][0], a1, b0); FMA2(acc2[1][1], a1, b1);
        FMA2(acc2[1][2], a1, b2); FMA2(acc2[1][3], a1, b3);
        FMA2(acc2[2][0], a2, b0); FMA2(acc2[2][1], a2, b1);
        FMA2(acc2[2][2], a2, b2); FMA2(acc2[2][3], a2, b3);
        FMA2(acc2[3][0], a3, b0); FMA2(acc2[3][1], a3, b1);
        FMA2(acc2[3][2], a3, b2); FMA2(acc2[3][3], a3, b3);
    }

    const int gn = n0 + (tx << 2);
    float bb[4];
    #pragma unroll
    for (int m = 0; m < 4; ++m) bb[m] = b_ih[gn + m] + b_hh[gn + m];

    #pragma unroll
    for (int i = 0; i < 4; ++i) {
        int gm = row0 + (ty << 2) + i;
        if (gm < VOCAB) {
            float r[4];
            #pragma unroll
            for (int m = 0; m < 4; ++m) {
                float lo, hi;
                asm("mov.b64 {%0,%1}, %2;" : "=f"(lo), "=f"(hi) : "l"(acc2[i][m]));
                r[m] = lo + hi + bb[m];
            }
            *reinterpret_cast<float4*>(g_P + (size_t)gm * GATES + gn) =
                make_float4(r[0], r[1], r[2], r[3]);
        }
    }
}

// ---------------------------------------------------------------------------
// Kernel 2: recurrent LSTM, cluster-of-2 K-split (R2 skeleton).
//   512 threads, thread j owns gate row j; rank r holds W_hh[j][64r..64r+63]
//   in registers. Per step: two 32-k chunks, chunk-A partials shipped via
//   st.async while chunk B computes (transit overlap); balanced xg fold.
// ---------------------------------------------------------------------------
__device__ __forceinline__ float sig_f(float x) {
    return __fdividef(1.f, 1.f + __expf(-x));
}
__device__ __forceinline__ float tanh_f(float x) {
    float e = __expf(fminf(-2.f * x, 30.f));
    return __fdividef(1.f - e, 1.f + e);
}
__device__ __forceinline__ unsigned cvta_smem(const void* p) {
    unsigned r;
    asm("{ .reg .u64 t; cvta.to.shared.u64 t, %1; cvt.u32.u64 %0, t; }"
        : "=r"(r) : "l"(p));
    return r;
}

#define MBWAIT(addr, par) do {                                                 \
    unsigned _done;                                                            \
    asm volatile(                                                              \
        "{\n\t.reg .pred p;\n\t"                                               \
        "mbarrier.try_wait.parity.acquire.cta.shared::cta.b64 p, [%1], %2;\n\t" \
        "selp.b32 %0, 1, 0, p;\n\t}"                                           \
        : "=r"(_done) : "r"(addr), "r"(par) : "memory");                       \
    if (!_done) {                                                              \
        asm volatile(                                                          \
            "{\n\t.reg .pred P1;\n\t"                                          \
            "WL_%=:\n\t"                                                       \
            "mbarrier.try_wait.parity.acquire.cta.shared::cta.b64 P1, [%0], %1, 0x989680;\n\t" \
            "@P1 bra.uni WD_%=;\n\t"                                           \
            "bra.uni WL_%=;\n\t"                                               \
            "WD_%=:\n\t}"                                                      \
            :: "r"(addr), "r"(par) : "memory");                                \
    }                                                                          \
} while (0)

__global__ __launch_bounds__(512, 1) __cluster_dims__(2, 1, 1)
void lstm_kernel(
    const int*   __restrict__ tokens,
    const float* __restrict__ W_hh,
    float*       __restrict__ out)
{
    __shared__ __align__(16) ull   mbar[1];
    __shared__ __align__(16) float h_s[128];
    __shared__ __align__(16) float a_s[512];
    __shared__ __align__(16) float pbuf[2][2][512];  // [buf][chunk][row]
    __shared__ int tok_s[SEQ];

    const int j    = threadIdx.x;
    const int b    = blockIdx.x >> 1;
    const int rank = blockIdx.x & 1;
    const int peer = rank ^ 1;

    const ull* W64 = (const ull*)W_hh;

    // Register-resident weight half: W_hh[j][64*rank .. 64*rank+63]
    ull wreg[32];
    #pragma unroll
    for (int kk = 0; kk < 32; ++kk)
        wreg[kk] = W64[(size_t)j * 64 + (rank << 5) + kk];

    for (int idx = j; idx < SEQ; idx += 512)
        tok_s[idx] = tokens[(size_t)b * SEQ + idx];

    if (j < 128) h_s[j] = 0.f;

    const unsigned mbar_a = cvta_smem(mbar);
    const unsigned pbuf_a = cvta_smem(pbuf);
    if (j == 0) {
        asm volatile("mbarrier.init.shared.b64 [%0], %1;"
                     :: "r"(mbar_a), "r"(1u) : "memory");
    }
    __syncthreads();
    asm volatile("barrier.cluster.arrive.aligned;" ::: "memory");
    asm volatile("barrier.cluster.wait.aligned;"   ::: "memory");

    unsigned rm_mbar, rm_pbuf;
    asm("mapa.shared::cluster.u32 %0, %1, %2;" : "=r"(rm_mbar) : "r"(mbar_a), "r"(peer));
    asm("mapa.shared::cluster.u32 %0, %1, %2;" : "=r"(rm_pbuf) : "r"(pbuf_a), "r"(peer));

    const float* Pp = (const float*)g_P;
    const bool fold = ((j >> 8) == rank);    // each rank folds xg for half the rows
    float x_cur = fold ? __ldg(Pp + (size_t)tok_s[0] * GATES + j) : 0.f;
    float c = 0.f;
    const bool sel_tanh = ((j >> 7) == 2);   // gate order i, f, g(tanh), o
    const ulonglong2* h2 = (const ulonglong2*)(h_s + (rank << 6));

    for (int t = 0; t < SEQ; ++t) {
        const int buf = t & 1;
        // arm this phase: 1 arrival + 4096 tx bytes (2 chunks x 512 x 4B)
        if (j == 0) {
            asm volatile("mbarrier.arrive.expect_tx.shared.b64 _, [%0], %1;"
                         :: "r"(mbar_a), "r"(4096u) : "memory");
        }

        float xg = x_cur;
        if (fold && t + 1 < SEQ)
            x_cur = __ldg(Pp + (size_t)tok_s[t + 1] * GATES + j);

        // ---- chunk A: k local 0..31 (4 chains, depth 4) ----
        ull a0 = 0ull, a1 = 0ull, a2 = 0ull, a3 = 0ull;
        #pragma unroll
        for (int q = 0; q < 4; ++q) {
            ulonglong2 A = h2[2 * q];
            ulonglong2 B = h2[2 * q + 1];
            FMA2(a0, wreg[4 * q + 0], A.x);
            FMA2(a1, wreg[4 * q + 1], A.y);
            FMA2(a2, wreg[4 * q + 2], B.x);
            FMA2(a3, wreg[4 * q + 3], B.y);
        }
        float sA;
        {
            float s0, s1, s2, s3, s4, s5, s6, s7;
            asm("mov.b64 {%0,%1}, %2;" : "=f"(s0), "=f"(s1) : "l"(a0));
            asm("mov.b64 {%0,%1}, %2;" : "=f"(s2), "=f"(s3) : "l"(a1));
            asm("mov.b64 {%0,%1}, %2;" : "=f"(s4), "=f"(s5) : "l"(a2));
            asm("mov.b64 {%0,%1}, %2;" : "=f"(s6), "=f"(s7) : "l"(a3));
            sA = ((s0 + s1) + (s2 + s3)) + ((s4 + s5) + (s6 + s7));
        }
        if (fold) sA += xg;
        {   // ship chunk A immediately; transit overlaps chunk B compute
            unsigned dst = rm_pbuf + (unsigned)((((buf << 1) + 0) * 512 + j) << 2);
            asm volatile(
                "st.async.shared::cluster.mbarrier::complete_tx::bytes.b32 [%0], %1, [%2];"
                :: "r"(dst), "r"(__float_as_uint(sA)), "r"(rm_mbar) : "memory");
        }

        // ---- chunk B: k local 32..63 (4 fresh chains) ----
        ull c0 = 0ull, c1 = 0ull, c2 = 0ull, c3 = 0ull;
        #pragma unroll
        for (int q = 4; q < 8; ++q) {
            ulonglong2 A = h2[2 * q];
            ulonglong2 B = h2[2 * q + 1];
            FMA2(c0, wreg[4 * q + 0], A.x);
            FMA2(c1, wreg[4 * q + 1], A.y);
            FMA2(c2, wreg[4 * q + 2], B.x);
            FMA2(c3, wreg[4 * q + 3], B.y);
        }
        float sB;
        {
            float s0, s1, s2, s3, s4, s5, s6, s7;
            asm("mov.b64 {%0,%1}, %2;" : "=f"(s0), "=f"(s1) : "l"(c0));
            asm("mov.b64 {%0,%1}, %2;" : "=f"(s2), "=f"(s3) : "l"(c1));
            asm("mov.b64 {%0,%1}, %2;" : "=f"(s4), "=f"(s5) : "l"(c2));
            asm("mov.b64 {%0,%1}, %2;" : "=f"(s6), "=f"(s7) : "l"(c3));
            sB = ((s0 + s1) + (s2 + s3)) + ((s4 + s5) + (s6 + s7));
        }
        {
            unsigned dst = rm_pbuf + (unsigned)((((buf << 1) + 1) * 512 + j) << 2);
            asm volatile(
                "st.async.shared::cluster.mbarrier::complete_tx::bytes.b32 [%0], %1, [%2];"
                :: "r"(dst), "r"(__float_as_uint(sB)), "r"(rm_mbar) : "memory");
        }
        float part = sA + sB;

        // wait for peer's 1024 partials (phase parity t&1)
        MBWAIT(mbar_a, (unsigned)(t & 1));

        float gsum = part + pbuf[buf][0][j] + pbuf[buf][1][j];
        float act = sel_tanh ? tanh_f(gsum) : sig_f(gsum);
        a_s[j] = act;
        __syncthreads();

        if (j < 128) {   // redundant tail on both ranks (keeps c, h local)
            float ai = a_s[j], af = a_s[128 + j], ag = a_s[256 + j], ao = a_s[384 + j];
            c = fmaf(af, c, ai * ag);
            h_s[j] = ao * tanh_f(c);
        }
        __syncthreads();
    }

    if (rank == 0 && j < 128) {
        out[(size_t)b * HID + j] = h_s[j];                        // h  [1,64,128]
        out[(size_t)BATCH * HID + (size_t)b * HID + j] = c;       // c  [1,64,128]
    }

    asm volatile("barrier.cluster.arrive.aligned;" ::: "memory");
    asm volatile("barrier.cluster.wait.aligned;"   ::: "memory");
}

// ---------------------------------------------------------------------------
extern "C" void kernel_launch(void* const* d_in, const int* in_sizes, int n_in,
                              void* d_out, int out_size)
{
    const int*   tokens = (const int*)  d_in[0];
    const float* emb    = (const float*)d_in[1];
    const float* W_ih   = (const float*)d_in[2];
    const float* W_hh   = (const float*)d_in[3];
    const float* b_ih   = (const float*)d_in[4];
    const float* b_hh   = (const float*)d_in[5];
    float* out = (float*)d_out;

    const int smem1 = 2 * 64 * 130 * (int)sizeof(float);   // 66560 B
    cudaFuncSetAttribute(proj_kernel, cudaFuncAttributeMaxDynamicSharedMemorySize, smem1);

    dim3 g1(GATES / 64, (VOCAB + 63) / 64);
    proj_kernel<<<g1, 256, smem1>>>(emb, W_ih, b_ih, b_hh);
    lstm_kernel<<<BATCH * 2, 512>>>(tokens, W_hh, out);
}